// round 15
// baseline (speedup 1.0000x reference)
#include <cuda_runtime.h>
#include <math.h>

#define NB   16
#define LQ   2048
#define LKK  2048
#define DIM  512
#define TOPK 512    // max(1, 2048/4)

// 256 MB fp32 scratch for dense scores / probabilities
__device__ float g_scores[67108864];  // 16 * 2048 * 2048

// ---------------------------------------------------------------------------
// packed f32x2 helpers (Blackwell FFMA2 path — only reachable via PTX)
// ---------------------------------------------------------------------------
__device__ __forceinline__ unsigned long long pk(float lo, float hi) {
    unsigned long long r;
    asm("mov.b64 %0, {%1, %2};" : "=l"(r) : "f"(lo), "f"(hi));
    return r;
}
__device__ __forceinline__ unsigned long long ffma2(unsigned long long a,
                                                    unsigned long long b,
                                                    unsigned long long c) {
    unsigned long long d;
    asm("fma.rn.f32x2 %0, %1, %2, %3;" : "=l"(d) : "l"(a), "l"(b), "l"(c));
    return d;
}
__device__ __forceinline__ float lo32(unsigned long long v) {
    return __uint_as_float((unsigned)v);
}
__device__ __forceinline__ float hi32(unsigned long long v) {
    return __uint_as_float((unsigned)(v >> 32));
}

// ---------------------------------------------------------------------------
// Kernel 1: S[b] = Q[b] (2048x512) * K[b]^T (512x2048) * scale
// 256x128 block tile, BK=8, 256 threads, 16x8 microtile, FFMA2, dbl-buffered.
// ---------------------------------------------------------------------------
__global__ __launch_bounds__(256) void gemm_qk_nt(const float* __restrict__ Q,
                                                  const float* __restrict__ K) {
    const int bm = blockIdx.x;   // LQ/256 = 8
    const int bn = blockIdx.y;   // LKK/128 = 16
    const int b  = blockIdx.z;

    const float* Qb = Q + ((size_t)b * LQ  + bm * 256) * DIM;
    const float* Kb = K + ((size_t)b * LKK + bn * 128) * DIM;

    __shared__ __align__(16) float As[2][8][264];   // [k][m], m=0..255
    __shared__ __align__(16) float Bs[2][8][136];   // [k][n], n=0..127

    const int tid = threadIdx.x;
    const int tx  = tid & 15;   // 16 threads * 8 cols  = 128 N
    const int ty  = tid >> 4;   // 16 threads * 16 rows = 256 M

    // A: each thread owns row `tid` (256 rows), 8 k-floats = 2 float4
    // B: rows 0..127, kq half selected by tid>>7
    const int rB  = tid & 127;
    const int kqB = (tid >> 7) * 4;

    unsigned long long acc[8][8];
#pragma unroll
    for (int i = 0; i < 8; ++i)
#pragma unroll
        for (int j = 0; j < 8; ++j) acc[i][j] = 0ull;

    // prologue: tile 0 -> buffer 0
    {
        float4 a0 = *(const float4*)(Qb + (size_t)tid * DIM + 0);
        float4 a1 = *(const float4*)(Qb + (size_t)tid * DIM + 4);
        float4 bv = *(const float4*)(Kb + (size_t)rB * DIM + kqB);
        As[0][0][tid] = a0.x; As[0][1][tid] = a0.y;
        As[0][2][tid] = a0.z; As[0][3][tid] = a0.w;
        As[0][4][tid] = a1.x; As[0][5][tid] = a1.y;
        As[0][6][tid] = a1.z; As[0][7][tid] = a1.w;
        Bs[0][kqB + 0][rB] = bv.x; Bs[0][kqB + 1][rB] = bv.y;
        Bs[0][kqB + 2][rB] = bv.z; Bs[0][kqB + 3][rB] = bv.w;
    }
    __syncthreads();

    const int KITER = DIM / 8;  // 64
    for (int it = 0; it < KITER; ++it) {
        const int cur = it & 1;
        const int nxt = cur ^ 1;
        float4 pa0, pa1, pb;
        const bool hasNext = (it + 1 < KITER);
        if (hasNext) {
            const int k0 = (it + 1) * 8;
            pa0 = *(const float4*)(Qb + (size_t)tid * DIM + k0 + 0);
            pa1 = *(const float4*)(Qb + (size_t)tid * DIM + k0 + 4);
            pb  = *(const float4*)(Kb + (size_t)rB  * DIM + k0 + kqB);
        }
#pragma unroll
        for (int kk = 0; kk < 8; ++kk) {
            const ulonglong2 a01 = *(const ulonglong2*)&As[cur][kk][ty * 16 + 0];
            const ulonglong2 a23 = *(const ulonglong2*)&As[cur][kk][ty * 16 + 4];
            const ulonglong2 a45 = *(const ulonglong2*)&As[cur][kk][ty * 16 + 8];
            const ulonglong2 a67 = *(const ulonglong2*)&As[cur][kk][ty * 16 + 12];
            const float4 b0 = *(const float4*)&Bs[cur][kk][tx * 8 + 0];
            const float4 b1 = *(const float4*)&Bs[cur][kk][tx * 8 + 4];
            unsigned long long ap[8] = {a01.x, a01.y, a23.x, a23.y,
                                        a45.x, a45.y, a67.x, a67.y};
            unsigned long long bp[8] = {
                pk(b0.x, b0.x), pk(b0.y, b0.y), pk(b0.z, b0.z), pk(b0.w, b0.w),
                pk(b1.x, b1.x), pk(b1.y, b1.y), pk(b1.z, b1.z), pk(b1.w, b1.w)};
#pragma unroll
            for (int i = 0; i < 8; ++i)
#pragma unroll
                for (int j = 0; j < 8; ++j)
                    acc[i][j] = ffma2(ap[i], bp[j], acc[i][j]);
        }
        if (hasNext) {
            As[nxt][0][tid] = pa0.x; As[nxt][1][tid] = pa0.y;
            As[nxt][2][tid] = pa0.z; As[nxt][3][tid] = pa0.w;
            As[nxt][4][tid] = pa1.x; As[nxt][5][tid] = pa1.y;
            As[nxt][6][tid] = pa1.z; As[nxt][7][tid] = pa1.w;
            Bs[nxt][kqB + 0][rB] = pb.x; Bs[nxt][kqB + 1][rB] = pb.y;
            Bs[nxt][kqB + 2][rB] = pb.z; Bs[nxt][kqB + 3][rB] = pb.w;
            __syncthreads();
        }
    }

    const float scale = 0.04419417382415922f;  // 1/sqrt(512)
    float* Sb = g_scores + (size_t)b * LQ * LKK
              + (size_t)(bm * 256 + ty * 16) * LKK + bn * 128 + tx * 8;
#pragma unroll
    for (int i = 0; i < 8; ++i) {
        float4 e0, e1, o0, o1;
        e0.x = lo32(acc[i][0]) * scale; e0.y = lo32(acc[i][1]) * scale;
        e0.z = lo32(acc[i][2]) * scale; e0.w = lo32(acc[i][3]) * scale;
        e1.x = lo32(acc[i][4]) * scale; e1.y = lo32(acc[i][5]) * scale;
        e1.z = lo32(acc[i][6]) * scale; e1.w = lo32(acc[i][7]) * scale;
        o0.x = hi32(acc[i][0]) * scale; o0.y = hi32(acc[i][1]) * scale;
        o0.z = hi32(acc[i][2]) * scale; o0.w = hi32(acc[i][3]) * scale;
        o1.x = hi32(acc[i][4]) * scale; o1.y = hi32(acc[i][5]) * scale;
        o1.z = hi32(acc[i][6]) * scale; o1.w = hi32(acc[i][7]) * scale;
        float* r0 = Sb + (size_t)(2 * i) * LKK;
        *(float4*)(r0)           = e0;
        *(float4*)(r0 + 4)       = e1;
        *(float4*)(r0 + LKK)     = o0;
        *(float4*)(r0 + LKK + 4) = o1;
    }
}

// ---------------------------------------------------------------------------
// Kernel 2: per (b,q) row — radix-select 512th-largest, masked softmax,
// write probabilities in place. Warp-shuffle scans (3 barriers/pass),
// race-safe snapshot -> barrier -> winner-write ordering.
// ---------------------------------------------------------------------------
__device__ __forceinline__ unsigned f2u(float f) {
    unsigned u = __float_as_uint(f);
    return (u & 0x80000000u) ? ~u : (u | 0x80000000u);
}
__device__ __forceinline__ float u2f(unsigned u) {
    unsigned b = (u & 0x80000000u) ? (u ^ 0x80000000u) : ~u;
    return __uint_as_float(b);
}

__global__ __launch_bounds__(256) void topk_softmax() {
    const size_t row = blockIdx.x;
    float* s = g_scores + row * (size_t)LKK;

    __shared__ unsigned keys[LKK];
    __shared__ unsigned hist[256];
    __shared__ unsigned warpsum[8];
    __shared__ float    redw[8];
    __shared__ unsigned warpmax[8];
    __shared__ unsigned sh_prefix, sh_want, sh_maxkey;

    const int tid  = threadIdx.x;
    const int lane = tid & 31;
    const int wid  = tid >> 5;

    // load + transform + row max
    unsigned lmax = 0;
    for (int i = tid; i < LKK; i += 256) {
        unsigned u = f2u(s[i]);
        keys[i] = u;
        lmax = max(lmax, u);
    }
    lmax = __reduce_max_sync(0xFFFFFFFFu, lmax);
    if (lane == 0) warpmax[wid] = lmax;
    __syncthreads();
    if (tid == 0) {
        unsigned m = warpmax[0];
#pragma unroll
        for (int w = 1; w < 8; ++w) m = max(m, warpmax[w]);
        sh_maxkey = m; sh_prefix = 0u; sh_want = TOPK;
    }
    __syncthreads();

    // 4-pass radix select (descending). Suffix sums via reversed warp scan.
#pragma unroll
    for (int pass = 0; pass < 4; ++pass) {
        const int shift = 24 - 8 * pass;
        hist[tid] = 0;
        __syncthreads();
        const unsigned prefix = sh_prefix;
        const unsigned pmask  = (pass == 0) ? 0u : (0xFFFFFFFFu << (32 - 8 * pass));
        for (int i = tid; i < LKK; i += 256) {
            unsigned u = keys[i];
            if ((u & pmask) == prefix) atomicAdd(&hist[(u >> shift) & 0xFFu], 1u);
        }
        __syncthreads();
        // thread tid handles bucket b = 255 - tid of the reversed array
        const unsigned v = hist[255 - tid];
        unsigned inc = v;
#pragma unroll
        for (int off = 1; off < 32; off <<= 1) {
            unsigned n = __shfl_up_sync(0xFFFFFFFFu, inc, off);
            if (lane >= off) inc += n;
        }
        if (lane == 31) warpsum[wid] = inc;
        __syncthreads();
        if (wid == 0 && lane < 8) {
            unsigned w = warpsum[lane];
            unsigned sc = w;
#pragma unroll
            for (int off = 1; off < 8; off <<= 1) {
                unsigned n = __shfl_up_sync(0xFFu, sc, off);
                if (lane >= off) sc += n;
            }
            warpsum[lane] = sc - w;  // exclusive
        }
        __syncthreads();
        const unsigned S_incl = inc + warpsum[wid];   // suf(b)   = sum_{j>=b} hist[j]
        const unsigned S_excl = S_incl - v;           // suf(b+1)
        const unsigned want   = sh_want;
        const bool     win    = (S_incl >= want) && (S_excl < want);
        const unsigned newWant = want - S_excl;
        __syncthreads();   // all reads of sh_want done before winner's write
        if (win) {
            sh_prefix = prefix | ((255u - (unsigned)tid) << shift);
            sh_want   = newWant;
        }
        __syncthreads();
    }
    const unsigned T = sh_prefix;   // key of the TOPK-th largest element
    const unsigned r = sh_want;     // keep first r elements equal to T

    // stable tie ranking: contiguous 8-element chunks, warp-scan prefix
    const int base = tid * (LKK / 256);
    unsigned myEq = 0;
#pragma unroll
    for (int j = 0; j < LKK / 256; ++j)
        if (keys[base + j] == T) myEq++;
    {
        unsigned inc = myEq;
#pragma unroll
        for (int off = 1; off < 32; off <<= 1) {
            unsigned n = __shfl_up_sync(0xFFFFFFFFu, inc, off);
            if (lane >= off) inc += n;
        }
        if (lane == 31) warpsum[wid] = inc;
        __syncthreads();
        if (wid == 0 && lane < 8) {
            unsigned w = warpsum[lane];
            unsigned sc = w;
#pragma unroll
            for (int off = 1; off < 8; off <<= 1) {
                unsigned n = __shfl_up_sync(0xFFu, sc, off);
                if (lane >= off) sc += n;
            }
            warpsum[lane] = sc - w;
        }
        __syncthreads();
        myEq = inc - myEq + warpsum[wid];  // exclusive prefix -> rank
    }
    unsigned rank = myEq;

    const float M = u2f(sh_maxkey);
    float lsum = 0.f;
#pragma unroll
    for (int j = 0; j < LKK / 256; ++j) {
        int i = base + j;
        unsigned u = keys[i];
        bool kept;
        if (u > T)       kept = true;
        else if (u == T) { kept = (rank < r); rank++; }
        else             kept = false;
        float p = kept ? __expf(u2f(u) - M) : 0.f;
        keys[i] = __float_as_uint(p);
        lsum += p;
    }
#pragma unroll
    for (int off = 16; off > 0; off >>= 1)
        lsum += __shfl_xor_sync(0xFFFFFFFFu, lsum, off);
    if (lane == 0) redw[wid] = lsum;
    __syncthreads();
    float tot = redw[0];
#pragma unroll
    for (int w = 1; w < 8; ++w) tot += redw[w];
    const float inv = 1.0f / tot;

#pragma unroll
    for (int j = 0; j < LKK / 256; j += 4) {
        float4 o;
        o.x = __uint_as_float(keys[base + j + 0]) * inv;
        o.y = __uint_as_float(keys[base + j + 1]) * inv;
        o.z = __uint_as_float(keys[base + j + 2]) * inv;
        o.w = __uint_as_float(keys[base + j + 3]) * inv;
        *(float4*)(s + base + j) = o;
    }
}

// ---------------------------------------------------------------------------
// Kernel 3: O[b] = P[b] (2048x2048) * V[b] (2048x512)
// 256x128 block tile, BK=8, 256 threads, 16x8 microtile, FFMA2, dbl-buffered.
// ---------------------------------------------------------------------------
__global__ __launch_bounds__(256) void gemm_pv_nn(const float* __restrict__ V,
                                                  float* __restrict__ O) {
    const int bm = blockIdx.x;   // LQ/256 = 8
    const int bn = blockIdx.y;   // DIM/128 = 4
    const int b  = blockIdx.z;

    const float* Pb = g_scores + (size_t)b * LQ * LKK + (size_t)(bm * 256) * LKK;
    const float* Vb = V + (size_t)b * LKK * DIM + bn * 128;

    __shared__ __align__(16) float As[2][8][264];   // [k][m] transposed P
    __shared__ __align__(16) float Bs[2][8][136];   // [k][n] direct V

    const int tid = threadIdx.x;
    const int tx  = tid & 15;
    const int ty  = tid >> 4;

    // B (V) slots: 8 k-rows x 128 n = 256 float4, one per thread
    const int kB = tid >> 5;          // 0..7
    const int cB = (tid & 31) * 4;    // 0..124

    unsigned long long acc[8][8];
#pragma unroll
    for (int i = 0; i < 8; ++i)
#pragma unroll
        for (int j = 0; j < 8; ++j) acc[i][j] = 0ull;

    {
        float4 a0 = *(const float4*)(Pb + (size_t)tid * LKK + 0);
        float4 a1 = *(const float4*)(Pb + (size_t)tid * LKK + 4);
        float4 bv = *(const float4*)(Vb + (size_t)kB * DIM + cB);
        As[0][0][tid] = a0.x; As[0][1][tid] = a0.y;
        As[0][2][tid] = a0.z; As[0][3][tid] = a0.w;
        As[0][4][tid] = a1.x; As[0][5][tid] = a1.y;
        As[0][6][tid] = a1.z; As[0][7][tid] = a1.w;
        *(float4*)&Bs[0][kB][cB] = bv;
    }
    __syncthreads();

    const int KITER = LKK / 8;  // 256
    for (int it = 0; it < KITER; ++it) {
        const int cur = it & 1;
        const int nxt = cur ^ 1;
        float4 pa0, pa1, pb;
        const bool hasNext = (it + 1 < KITER);
        if (hasNext) {
            const int k0 = (it + 1) * 8;
            pa0 = *(const float4*)(Pb + (size_t)tid * LKK + k0 + 0);
            pa1 = *(const float4*)(Pb + (size_t)tid * LKK + k0 + 4);
            pb  = *(const float4*)(Vb + (size_t)(k0 + kB) * DIM + cB);
        }
#pragma unroll
        for (int kk = 0; kk < 8; ++kk) {
            const ulonglong2 a01 = *(const ulonglong2*)&As[cur][kk][ty * 16 + 0];
            const ulonglong2 a23 = *(const ulonglong2*)&As[cur][kk][ty * 16 + 4];
            const ulonglong2 a45 = *(const ulonglong2*)&As[cur][kk][ty * 16 + 8];
            const ulonglong2 a67 = *(const ulonglong2*)&As[cur][kk][ty * 16 + 12];
            const float4 b0 = *(const float4*)&Bs[cur][kk][tx * 8 + 0];
            const float4 b1 = *(const float4*)&Bs[cur][kk][tx * 8 + 4];
            unsigned long long ap[8] = {a01.x, a01.y, a23.x, a23.y,
                                        a45.x, a45.y, a67.x, a67.y};
            unsigned long long bp[8] = {
                pk(b0.x, b0.x), pk(b0.y, b0.y), pk(b0.z, b0.z), pk(b0.w, b0.w),
                pk(b1.x, b1.x), pk(b1.y, b1.y), pk(b1.z, b1.z), pk(b1.w, b1.w)};
#pragma unroll
            for (int i = 0; i < 8; ++i)
#pragma unroll
                for (int j = 0; j < 8; ++j)
                    acc[i][j] = ffma2(ap[i], bp[j], acc[i][j]);
        }
        if (hasNext) {
            As[nxt][0][tid] = pa0.x; As[nxt][1][tid] = pa0.y;
            As[nxt][2][tid] = pa0.z; As[nxt][3][tid] = pa0.w;
            As[nxt][4][tid] = pa1.x; As[nxt][5][tid] = pa1.y;
            As[nxt][6][tid] = pa1.z; As[nxt][7][tid] = pa1.w;
            *(float4*)&Bs[nxt][kB][cB] = pb;
            __syncthreads();
        }
    }

    float* Ob = O + ((size_t)b * LQ + bm * 256 + ty * 16) * DIM + bn * 128 + tx * 8;
#pragma unroll
    for (int i = 0; i < 8; ++i) {
        float4 e0, e1, o0, o1;
        e0.x = lo32(acc[i][0]); e0.y = lo32(acc[i][1]);
        e0.z = lo32(acc[i][2]); e0.w = lo32(acc[i][3]);
        e1.x = lo32(acc[i][4]); e1.y = lo32(acc[i][5]);
        e1.z = lo32(acc[i][6]); e1.w = lo32(acc[i][7]);
        o0.x = hi32(acc[i][0]); o0.y = hi32(acc[i][1]);
        o0.z = hi32(acc[i][2]); o0.w = hi32(acc[i][3]);
        o1.x = hi32(acc[i][4]); o1.y = hi32(acc[i][5]);
        o1.z = hi32(acc[i][6]); o1.w = hi32(acc[i][7]);
        float* r0 = Ob + (size_t)(2 * i) * DIM;
        *(float4*)(r0)           = e0;
        *(float4*)(r0 + 4)       = e1;
        *(float4*)(r0 + DIM)     = o0;
        *(float4*)(r0 + DIM + 4) = o1;
    }
}

// ---------------------------------------------------------------------------
extern "C" void kernel_launch(void* const* d_in, const int* in_sizes, int n_in,
                              void* d_out, int out_size) {
    const float* Q = (const float*)d_in[0];
    const float* K = (const float*)d_in[1];
    const float* V = (const float*)d_in[2];
    // d_in[3] = mask: all-true in this problem, ignored.
    float* O = (float*)d_out;

    dim3 g1(LQ / 256, LKK / 128, NB);
    gemm_qk_nt<<<g1, 256>>>(Q, K);

    topk_softmax<<<NB * LQ, 256>>>();

    dim3 g3(LQ / 256, DIM / 128, NB);
    gemm_pv_nn<<<g3, 256>>>(V, O);
}